// round 3
// baseline (speedup 1.0000x reference)
#include <cuda_runtime.h>
#include <cuda_bf16.h>

#define B_IMGS 64
#define CH 3
#define H_MAX 512
#define W_STRIDE 513            // stored width is W_max+1
#define OUT_H 224
#define OUT_W 224

// Per-image lookup tables (precomputed each launch; deterministic).
// ytab: {y0*W_STRIDE, y1*W_STRIDE, bits(wy), 0}
// xtab: {x0, x1, bits(wx), 0}
__device__ int4 g_ytab[B_IMGS * OUT_H];
__device__ int4 g_xtab[B_IMGS * OUT_W];

__global__ __launch_bounds__(OUT_W) void precompute_kernel(const float* __restrict__ x)
{
    const int b = blockIdx.x;          // image
    const int t = threadIdx.x;         // 0..223 -> both oy and ox index

    const float* img = x + (size_t)b * CH * H_MAX * W_STRIDE;
    const float h = __ldg(img + (W_STRIDE - 1));
    const float w = __ldg(img + (size_t)H_MAX * W_STRIDE + (W_STRIDE - 1));

    const float min_dim = fminf(h, w);
    const float scale   = __fdiv_rn(256.0f, min_dim);   // IEEE rn
    const float h_res   = rintf(h * scale);             // half-to-even = jnp.round
    const float w_res   = rintf(w * scale);
    const float top     = rintf((h_res - (float)OUT_H) * 0.5f);
    const float left    = rintf((w_res - (float)OUT_W) * 0.5f);

    // ---- y entry (oy = t) ----
    {
        float sy = __fdiv_rn((((float)t + top) + 0.5f) * h, h_res) - 0.5f;
        sy = fminf(fmaxf(sy, 0.0f), h - 1.0f);
        const float y0f = floorf(sy);
        const float wy  = sy - y0f;
        const int hi = (int)h - 1;
        int y0 = min(max((int)y0f, 0), hi);
        const int y1 = min(y0 + 1, hi);
        g_ytab[b * OUT_H + t] =
            make_int4(y0 * W_STRIDE, y1 * W_STRIDE, __float_as_int(wy), 0);
    }
    // ---- x entry (ox = t) ----
    {
        float sx = __fdiv_rn((((float)t + left) + 0.5f) * w, w_res) - 0.5f;
        sx = fminf(fmaxf(sx, 0.0f), w - 1.0f);
        const float x0f = floorf(sx);
        const float wxv = sx - x0f;
        const int wi = (int)w - 1;
        int x0 = min(max((int)x0f, 0), wi);
        const int x1 = min(x0 + 1, wi);
        g_xtab[b * OUT_W + t] =
            make_int4(x0, x1, __float_as_int(wxv), 0);
    }
}

__global__ __launch_bounds__(OUT_W) void crop_main_kernel(
    const float* __restrict__ x, float* __restrict__ out)
{
    const int oy = blockIdx.x;         // 0..223
    const int b  = blockIdx.y;         // 0..63
    const int ox = threadIdx.x;        // 0..223

    // Broadcast load (same address across block) + coalesced LDG.128
    const int4 yt = g_ytab[b * OUT_H + oy];
    const int4 xt = g_xtab[b * OUT_W + ox];

    const float wy  = __int_as_float(yt.z);
    const float wxv = __int_as_float(xt.z);

    const float w00 = (1.0f - wy) * (1.0f - wxv);
    const float w01 = (1.0f - wy) * wxv;
    const float w10 = wy * (1.0f - wxv);
    const float w11 = wy * wxv;

    const float* img = x + (size_t)b * CH * H_MAX * W_STRIDE;
    const int a00 = yt.x + xt.x;   // r0 + x0
    const int a01 = yt.x + xt.y;   // r0 + x1
    const int a10 = yt.y + xt.x;   // r1 + x0
    const int a11 = yt.y + xt.y;   // r1 + x1

    float* o = out + (((size_t)b * CH) * OUT_H + oy) * OUT_W + ox;

#pragma unroll
    for (int c = 0; c < CH; c++) {
        const float* p = img + (size_t)c * (H_MAX * W_STRIDE);
        const float v00 = __ldg(p + a00);
        const float v01 = __ldg(p + a01);
        const float v10 = __ldg(p + a10);
        const float v11 = __ldg(p + a11);
        o[(size_t)c * (OUT_H * OUT_W)] =
            v00 * w00 + v01 * w01 + v10 * w10 + v11 * w11;
    }
}

extern "C" void kernel_launch(void* const* d_in, const int* in_sizes, int n_in,
                              void* d_out, int out_size)
{
    const float* x = (const float*)d_in[0];
    float* out = (float*)d_out;

    precompute_kernel<<<B_IMGS, OUT_W>>>(x);

    dim3 grid(OUT_H, B_IMGS);
    crop_main_kernel<<<grid, OUT_W>>>(x, out);
}

// round 5
// speedup vs baseline: 1.3249x; 1.3249x over previous
#include <cuda_runtime.h>
#include <cuda_bf16.h>

#define B_IMGS 64
#define CH 3
#define H_MAX 512
#define W_STRIDE 513            // stored width is W_max+1
#define OUT_H 224
#define OUT_W 224

__global__ __launch_bounds__(OUT_W) void center_crop2_kernel(
    const float* __restrict__ x, float* __restrict__ out)
{
    const int b   = blockIdx.y;            // 0..63
    const int oy0 = blockIdx.x * 2;        // 0,2,..,222 (pair of rows)
    const int ox  = threadIdx.x;           // 0..223

    const float* img = x + (size_t)b * CH * H_MAX * W_STRIDE;

    // h at x[b,0,0,W_max], w at x[b,1,0,W_max]  (broadcast loads)
    const float h = __ldg(img + (W_STRIDE - 1));
    const float w = __ldg(img + (size_t)H_MAX * W_STRIDE + (W_STRIDE - 1));

    // ---- discrete part: must be bit-exact vs XLA ----
    const float min_dim = fminf(h, w);
    const float scale   = __fdiv_rn(256.0f, min_dim);   // IEEE rn
    const float h_res   = rintf(h * scale);             // half-to-even = jnp.round
    const float w_res   = rintf(w * scale);
    const float top     = rintf((h_res - (float)OUT_H) * 0.5f);
    const float left    = rintf((w_res - (float)OUT_W) * 0.5f);

    // ---- continuous part: approx div OK (bilinear continuous in src coords) ----
    // x side (shared by both rows)
    float sx = __fdividef((((float)ox + left) + 0.5f) * w, w_res) - 0.5f;
    sx = fminf(fmaxf(sx, 0.0f), w - 1.0f);
    const float x0f = floorf(sx);
    const float wxv = sx - x0f;
    const int wi = (int)w - 1;
    int x0 = min(max((int)x0f, 0), wi);
    const int x1 = min(x0 + 1, wi);

    // y side, two rows
    const int hi = (int)h - 1;
    int   ya0[2], ya1[2];
    float wyv[2];
#pragma unroll
    for (int r = 0; r < 2; r++) {
        float sy = __fdividef((((float)(oy0 + r) + top) + 0.5f) * h, h_res) - 0.5f;
        sy = fminf(fmaxf(sy, 0.0f), h - 1.0f);
        const float y0f = floorf(sy);
        wyv[r] = sy - y0f;
        int y0 = min(max((int)y0f, 0), hi);
        const int y1 = min(y0 + 1, hi);
        ya0[r] = y0 * W_STRIDE;
        ya1[r] = y1 * W_STRIDE;
    }

    float* o = out + (((size_t)b * CH) * OUT_H + oy0) * OUT_W + ox;

#pragma unroll
    for (int c = 0; c < CH; c++) {
        const float* p = img + (size_t)c * (H_MAX * W_STRIDE);

        // issue all 8 gathers for this channel (2 rows x 4 taps) before math
        float v00a = __ldg(p + ya0[0] + x0);
        float v01a = __ldg(p + ya0[0] + x1);
        float v10a = __ldg(p + ya1[0] + x0);
        float v11a = __ldg(p + ya1[0] + x1);
        float v00b = __ldg(p + ya0[1] + x0);
        float v01b = __ldg(p + ya0[1] + x1);
        float v10b = __ldg(p + ya1[1] + x0);
        float v11b = __ldg(p + ya1[1] + x1);

        {
            const float wy = wyv[0];
            const float top_v = v00a + (v01a - v00a) * wxv;
            const float bot_v = v10a + (v11a - v10a) * wxv;
            o[(size_t)c * (OUT_H * OUT_W)] = top_v + (bot_v - top_v) * wy;
        }
        {
            const float wy = wyv[1];
            const float top_v = v00b + (v01b - v00b) * wxv;
            const float bot_v = v10b + (v11b - v10b) * wxv;
            o[(size_t)c * (OUT_H * OUT_W) + OUT_W] = top_v + (bot_v - top_v) * wy;
        }
    }
}

extern "C" void kernel_launch(void* const* d_in, const int* in_sizes, int n_in,
                              void* d_out, int out_size)
{
    const float* x = (const float*)d_in[0];
    float* out = (float*)d_out;
    dim3 grid(OUT_H / 2, B_IMGS);
    center_crop2_kernel<<<grid, OUT_W>>>(x, out);
}